// round 15
// baseline (speedup 1.0000x reference)
#include <cuda_runtime.h>
#include <math_constants.h>

#define EMBED   1024
#define NH      16
#define HD      64
#define CACHE   16384
#define NBLK    148               // one block per SM, grid-stride over rows
#define WPB     10                // warps per block (320 threads)
#define NW      (NBLK * WPB)      // total warps = 1480
#define GCS     4                 // GEMV column chunks (64 float4 columns each)
#define GRS     32                // GEMV row chunks -> 32 atomic writers per address
#define GROWS   (EMBED / GRS)     // 32 rows per block
#define GTROWS  (GROWS / 4)       // 8 rows per thread
#define WELEM   (EMBED * EMBED / 4)   // 65536 float4 per weight matrix

// ---------------- device scratch (no allocations allowed) ----------------
__device__ __align__(16) float g_qkv[3 * EMBED];   // [0]=q, [1]=k_i, [2]=v_i (with bias)
__device__ __align__(16) float g_values[EMBED];    // unnormalized attention output
__device__ __align__(16) float g_l[NH];            // sum-exp per head
__device__ float g_sink;                           // DCE-prevention sink (never written)

// ---------------- zero accumulators + warm all weights into L2 ----------------
__global__ __launch_bounds__(256) void warm_zero_kernel(float* __restrict__ out,
                                                        const float4* __restrict__ Wq,
                                                        const float4* __restrict__ Wk,
                                                        const float4* __restrict__ Wv,
                                                        const float4* __restrict__ Wo) {
    const int i = blockIdx.x * blockDim.x + threadIdx.x;   // 0..65535
    if (i < 3 * EMBED)           g_qkv[i]                = 0.f;
    else if (i < 4 * EMBED)      g_values[i - 3 * EMBED] = 0.f;
    else if (i < 5 * EMBED)      out[i - 4 * EMBED]      = 0.f;
    else if (i < 5 * EMBED + NH) g_l[i - 5 * EMBED]      = 0.f;

    // warm: one fully-independent L2 load per matrix per thread
    const float4 a = __ldcg(&Wq[i]);
    const float4 b = __ldcg(&Wk[i]);
    const float4 c = __ldcg(&Wv[i]);
    const float4 d = __ldcg(&Wo[i]);
    const float s = a.x + b.y + c.z + d.w;
    if (s == -1.2345e38f) g_sink = s;   // never true; defeats DCE
}

// ---------------- shared GEMV tile body: 64 cols x 32 rows (L2-resident weights) ----------------
__device__ __forceinline__ float4 gemv_tile(const float4* __restrict__ W4,
                                            const float* __restrict__ xs,
                                            int r0, int rloc, int col) {
    float4 w[GTROWS];
#pragma unroll
    for (int i = 0; i < GTROWS; ++i)
        w[i] = W4[(size_t)(r0 + i) * 256 + col];
    float4 a = make_float4(0.f, 0.f, 0.f, 0.f);
#pragma unroll
    for (int i = 0; i < GTROWS; ++i) {
        const float s = xs[rloc + i];
        a.x += s * w[i].x; a.y += s * w[i].y;
        a.z += s * w[i].z; a.w += s * w[i].w;
    }
    return a;
}

__device__ __forceinline__ void gemv_reduce_store(float4 a, int rgrp, int lcol, int col,
                                                  int rchk, const float* __restrict__ bias,
                                                  float* __restrict__ dst_base) {
    __shared__ float4 sred[4][64];
    sred[rgrp][lcol] = a;
    __syncthreads();
    if (threadIdx.x < 64) {
        const float4 t0 = sred[0][threadIdx.x], t1 = sred[1][threadIdx.x];
        const float4 t2 = sred[2][threadIdx.x], t3 = sred[3][threadIdx.x];
        float4 r;
        r.x = (t0.x + t1.x) + (t2.x + t3.x);
        r.y = (t0.y + t1.y) + (t2.y + t3.y);
        r.z = (t0.z + t1.z) + (t2.z + t3.z);
        r.w = (t0.w + t1.w) + (t2.w + t3.w);
        if (rchk == 0) {
            const float4 b4 = reinterpret_cast<const float4*>(bias)[col];
            r.x += b4.x; r.y += b4.y; r.z += b4.z; r.w += b4.w;
        }
        atomicAdd(dst_base + col * 4 + 0, r.x);
        atomicAdd(dst_base + col * 4 + 1, r.y);
        atomicAdd(dst_base + col * 4 + 2, r.z);
        atomicAdd(dst_base + col * 4 + 3, r.w);
    }
}

// ---------------- K0: q/k/v projections ----------------
__global__ __launch_bounds__(256) void proj_qkv(const float* __restrict__ x,
                                                const float* __restrict__ Wq,
                                                const float* __restrict__ Wk,
                                                const float* __restrict__ Wv,
                                                const float* __restrict__ bq,
                                                const float* __restrict__ bk,
                                                const float* __restrict__ bv) {
    const int mat  = blockIdx.x / GCS;              // 0=q,1=k,2=v
    const int cchk = blockIdx.x % GCS;
    const int rchk = blockIdx.y;                    // 0..31
    const int lcol = threadIdx.x & 63;
    const int col  = cchk * 64 + lcol;
    const int rgrp = threadIdx.x >> 6;              // 0..3
    const int r0   = rchk * GROWS + rgrp * GTROWS;
    const float* W = (mat == 0) ? Wq : (mat == 1) ? Wk : Wv;
    const float* b = (mat == 0) ? bq : (mat == 1) ? bk : bv;

    __shared__ float xs[GROWS];
    if (threadIdx.x < GROWS) xs[threadIdx.x] = x[rchk * GROWS + threadIdx.x];
    __syncthreads();

    const float4 a = gemv_tile(reinterpret_cast<const float4*>(W), xs,
                               r0, rgrp * GTROWS, col);
    gemv_reduce_store(a, rgrp, lcol, col, rchk, b, &g_qkv[mat * EMBED]);
}

// ---------------- K1: warp-per-row fused shift + attention (no block barriers) ----------------
__global__ __launch_bounds__(320, 1) void fused_shift_attn(const float* __restrict__ cache,
                                                           float* __restrict__ out) {
    const int lane = threadIdx.x & 31;
    const int wid  = threadIdx.x >> 5;              // warp in block 0..9
    const int gw   = blockIdx.x * WPB + wid;        // global warp 0..1479

    const float4* cv = reinterpret_cast<const float4*>(cache);
    const float4* ck = reinterpret_cast<const float4*>(cache + (size_t)CACHE * EMBED);
    const float4* qf = reinterpret_cast<const float4*>(g_qkv);
    const float4* kf = reinterpret_cast<const float4*>(g_qkv + EMBED);
    const float4* vf = reinterpret_cast<const float4*>(g_qkv + 2 * EMBED);
    float4* outv = reinterpret_cast<float4*>(out + EMBED);
    float4* outk = reinterpret_cast<float4*>(out + EMBED + (size_t)CACHE * EMBED);

    float4 q4[8];
#pragma unroll
    for (int j = 0; j < 8; ++j) q4[j] = qf[lane + 32 * j];

    float4 acc[8];
    float  lsum[8];
#pragma unroll
    for (int j = 0; j < 8; ++j) {
        acc[j] = make_float4(0.f, 0.f, 0.f, 0.f);
        lsum[j] = 0.f;
    }

    for (int t = gw; t < CACHE; t += NW) {
        float4 v4[8], k4[8];
        if (t == CACHE - 1) {
#pragma unroll
            for (int j = 0; j < 8; ++j) {
                v4[j] = vf[lane + 32 * j];
                k4[j] = kf[lane + 32 * j];
            }
        } else {
            const size_t base = (size_t)(t + 1) * 256;
#pragma unroll
            for (int j = 0; j < 8; ++j) {
                v4[j] = __ldcs(&cv[base + lane + 32 * j]);
                k4[j] = __ldcs(&ck[base + lane + 32 * j]);
            }
        }

        const size_t ob = (size_t)t * 256;
#pragma unroll
        for (int j = 0; j < 8; ++j) {
            __stcs(&outv[ob + lane + 32 * j], v4[j]);
            __stcs(&outk[ob + lane + 32 * j], k4[j]);
        }

        int nz = 0;
#pragma unroll
        for (int j = 0; j < 8; ++j)
            nz |= (v4[j].x != 0.f) | (v4[j].y != 0.f) |
                  (v4[j].z != 0.f) | (v4[j].w != 0.f);
        const int valid = __any_sync(0xffffffffu, nz);

#pragma unroll
        for (int j = 0; j < 8; ++j) {
            float pd = q4[j].x * k4[j].x + q4[j].y * k4[j].y +
                       q4[j].z * k4[j].z + q4[j].w * k4[j].w;
            pd += __shfl_xor_sync(0xffffffffu, pd, 1);
            pd += __shfl_xor_sync(0xffffffffu, pd, 2);
            pd += __shfl_xor_sync(0xffffffffu, pd, 4);
            pd += __shfl_xor_sync(0xffffffffu, pd, 8);
            if (valid) {
                const float p = __expf(pd * 0.125f);   // no-max softmax (bounded logits)
                lsum[j] += p;
                acc[j].x += p * v4[j].x;
                acc[j].y += p * v4[j].y;
                acc[j].z += p * v4[j].z;
                acc[j].w += p * v4[j].w;
            }
        }
    }

    __shared__ float4 sacc[WPB * 256];
    __shared__ float  sl[WPB][NH];
#pragma unroll
    for (int j = 0; j < 8; ++j) {
        const int h  = 2 * j + (lane >> 4);
        const int gi = h * 16 + (lane & 15);
        sacc[wid * 256 + gi] = acc[j];
        if ((lane & 15) == 0) sl[wid][h] = lsum[j];
    }
    __syncthreads();

    const int tid = threadIdx.x;
    if (tid < 256) {
        float4 tot = sacc[tid];
#pragma unroll
        for (int w = 1; w < WPB; ++w) {
            const float4 o = sacc[w * 256 + tid];
            tot.x += o.x; tot.y += o.y; tot.z += o.z; tot.w += o.w;
        }
        atomicAdd(&g_values[tid * 4 + 0], tot.x);
        atomicAdd(&g_values[tid * 4 + 1], tot.y);
        atomicAdd(&g_values[tid * 4 + 2], tot.z);
        atomicAdd(&g_values[tid * 4 + 3], tot.w);
        if (tid < NH) {
            float s = 0.f;
#pragma unroll
            for (int w = 0; w < WPB; ++w) s += sl[w][tid];
            atomicAdd(&g_l[tid], s);
        }
    }
}

// ---------------- K3: output projection ----------------
__global__ __launch_bounds__(256) void proj_out(const float* __restrict__ Wo,
                                                const float* __restrict__ bo,
                                                float* __restrict__ out) {
    const int cchk = blockIdx.x;                    // 0..3
    const int rchk = blockIdx.y;                    // 0..31
    const int lcol = threadIdx.x & 63;
    const int col  = cchk * 64 + lcol;
    const int rgrp = threadIdx.x >> 6;
    const int r0   = rchk * GROWS + rgrp * GTROWS;

    __shared__ float xs[GROWS];
    if (threadIdx.x < GROWS) {
        const int src = rchk * GROWS + threadIdx.x;
        xs[threadIdx.x] = g_values[src] / g_l[src >> 6];   // fold softmax denom here
    }
    __syncthreads();

    const float4 a = gemv_tile(reinterpret_cast<const float4*>(Wo), xs,
                               r0, rgrp * GTROWS, col);
    gemv_reduce_store(a, rgrp, lcol, col, rchk, bo, out);
}

// ---------------- launch ----------------
extern "C" void kernel_launch(void* const* d_in, const int* in_sizes, int n_in,
                              void* d_out, int out_size) {
    const float* x     = (const float*)d_in[0];
    const float* cache = (const float*)d_in[1];
    const float* Wv    = (const float*)d_in[2];
    const float* bv    = (const float*)d_in[3];
    const float* Wq    = (const float*)d_in[4];
    const float* bq    = (const float*)d_in[5];
    const float* Wk    = (const float*)d_in[6];
    const float* bk    = (const float*)d_in[7];
    const float* Wo    = (const float*)d_in[8];
    const float* bo    = (const float*)d_in[9];
    float* out = (float*)d_out;

    warm_zero_kernel<<<WELEM / 256, 256>>>(out,
                                           (const float4*)Wq, (const float4*)Wk,
                                           (const float4*)Wv, (const float4*)Wo);
    proj_qkv<<<dim3(3 * GCS, GRS), 256>>>(x, Wq, Wk, Wv, bq, bk, bv);
    fused_shift_attn<<<NBLK, 32 * WPB>>>(cache, out);
    proj_out<<<dim3(GCS, GRS), 256>>>(Wo, bo, out);
}

// round 17
// speedup vs baseline: 1.0133x; 1.0133x over previous
#include <cuda_runtime.h>
#include <math_constants.h>

#define EMBED   1024
#define NH      16
#define HD      64
#define CACHE   16384
#define NBLK    148               // one block per SM, grid-stride over rows
#define WPB     10                // warps per block (320 threads)
#define NW      (NBLK * WPB)      // total warps = 1480
#define GCS     4                 // GEMV column chunks (64 float4 columns each)
#define GRS     32                // GEMV row chunks -> 32 atomic writers per address
#define GROWS   (EMBED / GRS)     // 32 rows per block
#define GTROWS  (GROWS / 4)       // 8 rows per thread

// ---------------- device scratch (no allocations allowed) ----------------
__device__ __align__(16) float g_qkv[3 * EMBED];   // [0]=q, [1]=k_i, [2]=v_i (with bias)
__device__ __align__(16) float g_values[EMBED];    // unnormalized attention output
__device__ __align__(16) float g_l[NH];            // sum-exp per head

// ---------------- zero accumulators each replay ----------------
__global__ void zero_kernel(float* __restrict__ out) {
    const int i = blockIdx.x * blockDim.x + threadIdx.x;   // 0..5375
    if (i < 3 * EMBED)           g_qkv[i]                = 0.f;
    else if (i < 4 * EMBED)      g_values[i - 3 * EMBED] = 0.f;
    else if (i < 5 * EMBED)      out[i - 4 * EMBED]      = 0.f;
    else if (i < 5 * EMBED + NH) g_l[i - 5 * EMBED]      = 0.f;
}

// ---------------- ISA-forced non-coherent vector load (cannot be collapsed) ----------------
__device__ __forceinline__ float4 ldg_nc_v4(const float4* p) {
    float4 v;
    asm volatile("ld.global.nc.v4.f32 {%0,%1,%2,%3}, [%4];"
                 : "=f"(v.x), "=f"(v.y), "=f"(v.z), "=f"(v.w)
                 : "l"(p));
    return v;
}

// ---------------- GEMV tile body: 8 forced-in-flight row loads per thread ----------------
__device__ __forceinline__ float4 gemv_tile(const float4* __restrict__ W4,
                                            const float* __restrict__ xs,
                                            int r0, int rloc, int col) {
    // 8 volatile asm loads: must issue back-to-back, 32 dest regs live -> true MLP=8
    const float4 w0 = ldg_nc_v4(&W4[(size_t)(r0 + 0) * 256 + col]);
    const float4 w1 = ldg_nc_v4(&W4[(size_t)(r0 + 1) * 256 + col]);
    const float4 w2 = ldg_nc_v4(&W4[(size_t)(r0 + 2) * 256 + col]);
    const float4 w3 = ldg_nc_v4(&W4[(size_t)(r0 + 3) * 256 + col]);
    const float4 w4 = ldg_nc_v4(&W4[(size_t)(r0 + 4) * 256 + col]);
    const float4 w5 = ldg_nc_v4(&W4[(size_t)(r0 + 5) * 256 + col]);
    const float4 w6 = ldg_nc_v4(&W4[(size_t)(r0 + 6) * 256 + col]);
    const float4 w7 = ldg_nc_v4(&W4[(size_t)(r0 + 7) * 256 + col]);

    float4 a = make_float4(0.f, 0.f, 0.f, 0.f);
    float s;
    s = xs[rloc + 0]; a.x += s * w0.x; a.y += s * w0.y; a.z += s * w0.z; a.w += s * w0.w;
    s = xs[rloc + 1]; a.x += s * w1.x; a.y += s * w1.y; a.z += s * w1.z; a.w += s * w1.w;
    s = xs[rloc + 2]; a.x += s * w2.x; a.y += s * w2.y; a.z += s * w2.z; a.w += s * w2.w;
    s = xs[rloc + 3]; a.x += s * w3.x; a.y += s * w3.y; a.z += s * w3.z; a.w += s * w3.w;
    s = xs[rloc + 4]; a.x += s * w4.x; a.y += s * w4.y; a.z += s * w4.z; a.w += s * w4.w;
    s = xs[rloc + 5]; a.x += s * w5.x; a.y += s * w5.y; a.z += s * w5.z; a.w += s * w5.w;
    s = xs[rloc + 6]; a.x += s * w6.x; a.y += s * w6.y; a.z += s * w6.z; a.w += s * w6.w;
    s = xs[rloc + 7]; a.x += s * w7.x; a.y += s * w7.y; a.z += s * w7.z; a.w += s * w7.w;
    return a;
}

__device__ __forceinline__ void gemv_reduce_store(float4 a, int rgrp, int lcol, int col,
                                                  int rchk, const float* __restrict__ bias,
                                                  float* __restrict__ dst_base) {
    __shared__ float4 sred[4][64];
    sred[rgrp][lcol] = a;
    __syncthreads();
    if (threadIdx.x < 64) {
        const float4 t0 = sred[0][threadIdx.x], t1 = sred[1][threadIdx.x];
        const float4 t2 = sred[2][threadIdx.x], t3 = sred[3][threadIdx.x];
        float4 r;
        r.x = (t0.x + t1.x) + (t2.x + t3.x);
        r.y = (t0.y + t1.y) + (t2.y + t3.y);
        r.z = (t0.z + t1.z) + (t2.z + t3.z);
        r.w = (t0.w + t1.w) + (t2.w + t3.w);
        if (rchk == 0) {
            const float4 b4 = reinterpret_cast<const float4*>(bias)[col];
            r.x += b4.x; r.y += b4.y; r.z += b4.z; r.w += b4.w;
        }
        atomicAdd(dst_base + col * 4 + 0, r.x);
        atomicAdd(dst_base + col * 4 + 1, r.y);
        atomicAdd(dst_base + col * 4 + 2, r.z);
        atomicAdd(dst_base + col * 4 + 3, r.w);
    }
}

// ---------------- K0: q/k/v projections ----------------
__global__ __launch_bounds__(256) void proj_qkv(const float* __restrict__ x,
                                                const float* __restrict__ Wq,
                                                const float* __restrict__ Wk,
                                                const float* __restrict__ Wv,
                                                const float* __restrict__ bq,
                                                const float* __restrict__ bk,
                                                const float* __restrict__ bv) {
    const int mat  = blockIdx.x / GCS;              // 0=q,1=k,2=v
    const int cchk = blockIdx.x % GCS;
    const int rchk = blockIdx.y;                    // 0..31
    const int lcol = threadIdx.x & 63;
    const int col  = cchk * 64 + lcol;
    const int rgrp = threadIdx.x >> 6;              // 0..3
    const int r0   = rchk * GROWS + rgrp * GTROWS;
    const float* W = (mat == 0) ? Wq : (mat == 1) ? Wk : Wv;
    const float* b = (mat == 0) ? bq : (mat == 1) ? bk : bv;

    __shared__ float xs[GROWS];
    if (threadIdx.x < GROWS) xs[threadIdx.x] = x[rchk * GROWS + threadIdx.x];
    __syncthreads();

    const float4 a = gemv_tile(reinterpret_cast<const float4*>(W), xs,
                               r0, rgrp * GTROWS, col);
    gemv_reduce_store(a, rgrp, lcol, col, rchk, b, &g_qkv[mat * EMBED]);
}

// ---------------- K1: warp-per-row fused shift + attention (no block barriers) ----------------
__global__ __launch_bounds__(320, 1) void fused_shift_attn(const float* __restrict__ cache,
                                                           float* __restrict__ out) {
    const int lane = threadIdx.x & 31;
    const int wid  = threadIdx.x >> 5;              // warp in block 0..9
    const int gw   = blockIdx.x * WPB + wid;        // global warp 0..1479

    const float4* cv = reinterpret_cast<const float4*>(cache);
    const float4* ck = reinterpret_cast<const float4*>(cache + (size_t)CACHE * EMBED);
    const float4* qf = reinterpret_cast<const float4*>(g_qkv);
    const float4* kf = reinterpret_cast<const float4*>(g_qkv + EMBED);
    const float4* vf = reinterpret_cast<const float4*>(g_qkv + 2 * EMBED);
    float4* outv = reinterpret_cast<float4*>(out + EMBED);
    float4* outk = reinterpret_cast<float4*>(out + EMBED + (size_t)CACHE * EMBED);

    float4 q4[8];
#pragma unroll
    for (int j = 0; j < 8; ++j) q4[j] = qf[lane + 32 * j];

    float4 acc[8];
    float  lsum[8];
#pragma unroll
    for (int j = 0; j < 8; ++j) {
        acc[j] = make_float4(0.f, 0.f, 0.f, 0.f);
        lsum[j] = 0.f;
    }

    for (int t = gw; t < CACHE; t += NW) {
        float4 v4[8], k4[8];
        if (t == CACHE - 1) {
#pragma unroll
            for (int j = 0; j < 8; ++j) {
                v4[j] = vf[lane + 32 * j];
                k4[j] = kf[lane + 32 * j];
            }
        } else {
            const size_t base = (size_t)(t + 1) * 256;
#pragma unroll
            for (int j = 0; j < 8; ++j) {
                v4[j] = __ldcs(&cv[base + lane + 32 * j]);
                k4[j] = __ldcs(&ck[base + lane + 32 * j]);
            }
        }

        const size_t ob = (size_t)t * 256;
#pragma unroll
        for (int j = 0; j < 8; ++j) {
            __stcs(&outv[ob + lane + 32 * j], v4[j]);
            __stcs(&outk[ob + lane + 32 * j], k4[j]);
        }

        int nz = 0;
#pragma unroll
        for (int j = 0; j < 8; ++j)
            nz |= (v4[j].x != 0.f) | (v4[j].y != 0.f) |
                  (v4[j].z != 0.f) | (v4[j].w != 0.f);
        const int valid = __any_sync(0xffffffffu, nz);

#pragma unroll
        for (int j = 0; j < 8; ++j) {
            float pd = q4[j].x * k4[j].x + q4[j].y * k4[j].y +
                       q4[j].z * k4[j].z + q4[j].w * k4[j].w;
            pd += __shfl_xor_sync(0xffffffffu, pd, 1);
            pd += __shfl_xor_sync(0xffffffffu, pd, 2);
            pd += __shfl_xor_sync(0xffffffffu, pd, 4);
            pd += __shfl_xor_sync(0xffffffffu, pd, 8);
            if (valid) {
                const float p = __expf(pd * 0.125f);   // no-max softmax (bounded logits)
                lsum[j] += p;
                acc[j].x += p * v4[j].x;
                acc[j].y += p * v4[j].y;
                acc[j].z += p * v4[j].z;
                acc[j].w += p * v4[j].w;
            }
        }
    }

    __shared__ float4 sacc[WPB * 256];
    __shared__ float  sl[WPB][NH];
#pragma unroll
    for (int j = 0; j < 8; ++j) {
        const int h  = 2 * j + (lane >> 4);
        const int gi = h * 16 + (lane & 15);
        sacc[wid * 256 + gi] = acc[j];
        if ((lane & 15) == 0) sl[wid][h] = lsum[j];
    }
    __syncthreads();

    const int tid = threadIdx.x;
    if (tid < 256) {
        float4 tot = sacc[tid];
#pragma unroll
        for (int w = 1; w < WPB; ++w) {
            const float4 o = sacc[w * 256 + tid];
            tot.x += o.x; tot.y += o.y; tot.z += o.z; tot.w += o.w;
        }
        atomicAdd(&g_values[tid * 4 + 0], tot.x);
        atomicAdd(&g_values[tid * 4 + 1], tot.y);
        atomicAdd(&g_values[tid * 4 + 2], tot.z);
        atomicAdd(&g_values[tid * 4 + 3], tot.w);
        if (tid < NH) {
            float s = 0.f;
#pragma unroll
            for (int w = 0; w < WPB; ++w) s += sl[w][tid];
            atomicAdd(&g_l[tid], s);
        }
    }
}

// ---------------- K3: output projection ----------------
__global__ __launch_bounds__(256) void proj_out(const float* __restrict__ Wo,
                                                const float* __restrict__ bo,
                                                float* __restrict__ out) {
    const int cchk = blockIdx.x;                    // 0..3
    const int rchk = blockIdx.y;                    // 0..31
    const int lcol = threadIdx.x & 63;
    const int col  = cchk * 64 + lcol;
    const int rgrp = threadIdx.x >> 6;
    const int r0   = rchk * GROWS + rgrp * GTROWS;

    __shared__ float xs[GROWS];
    if (threadIdx.x < GROWS) {
        const int src = rchk * GROWS + threadIdx.x;
        xs[threadIdx.x] = g_values[src] / g_l[src >> 6];   // fold softmax denom here
    }
    __syncthreads();

    const float4 a = gemv_tile(reinterpret_cast<const float4*>(Wo), xs,
                               r0, rgrp * GTROWS, col);
    gemv_reduce_store(a, rgrp, lcol, col, rchk, bo, out);
}

// ---------------- launch ----------------
extern "C" void kernel_launch(void* const* d_in, const int* in_sizes, int n_in,
                              void* d_out, int out_size) {
    const float* x     = (const float*)d_in[0];
    const float* cache = (const float*)d_in[1];
    const float* Wv    = (const float*)d_in[2];
    const float* bv    = (const float*)d_in[3];
    const float* Wq    = (const float*)d_in[4];
    const float* bq    = (const float*)d_in[5];
    const float* Wk    = (const float*)d_in[6];
    const float* bk    = (const float*)d_in[7];
    const float* Wo    = (const float*)d_in[8];
    const float* bo    = (const float*)d_in[9];
    float* out = (float*)d_out;

    zero_kernel<<<21, 256>>>(out);
    proj_qkv<<<dim3(3 * GCS, GRS), 256>>>(x, Wq, Wk, Wv, bq, bk, bv);
    fused_shift_attn<<<NBLK, 32 * WPB>>>(cache, out);
    proj_out<<<dim3(GCS, GRS), 256>>>(Wo, bo, out);
}